// round 1
// baseline (speedup 1.0000x reference)
#include <cuda_runtime.h>
#include <cuda_bf16.h>

#define BATCH 4
#define CTX   2048
#define NEMB  1024
#define NH    16
#define HS    64
#define DM    (NH*HS)      // 1024
#define FF    (4*DM)       // 4096

// ---------------- scratch (device globals; no allocation) ----------------
__device__ float g_q[(size_t)BATCH*NH*CTX*HS];   // [B,H,T,D]
__device__ float g_k[(size_t)BATCH*NH*CTX*HS];
__device__ float g_v[(size_t)BATCH*NH*CTX*HS];
__device__ float g_att[(size_t)BATCH*CTX*DM];    // [B,T,H*D]
__device__ float g_h[(size_t)BATCH*CTX*FF];      // [B*T, 4*DM]

// ---------------- kernel 1: QKV projection ----------------
// grid: (CTX/128, NH*3, BATCH), 256 threads
// per block: X_b[128,1024] @ W_{sel,h}[1024,64] -> q/k/v[b,h,tile,:]
__global__ __launch_bounds__(256)
void qkv_kernel(const float* __restrict__ x,
                const float* __restrict__ Wq,
                const float* __restrict__ Wk,
                const float* __restrict__ Wv)
{
    int tile_m = blockIdx.x;
    int h   = blockIdx.y % NH;
    int sel = blockIdx.y / NH;
    int b   = blockIdx.z;

    const float* W = (sel == 0 ? Wq : (sel == 1 ? Wk : Wv)) + (size_t)h * NEMB * HS;
    const float* A = x + (size_t)b * CTX * NEMB + (size_t)tile_m * 128 * NEMB;
    float* out = (sel == 0 ? g_q : (sel == 1 ? g_k : g_v))
                 + ((size_t)(b * NH + h) * CTX + (size_t)tile_m * 128) * HS;

    __shared__ float As[16][128];
    __shared__ float Bs[16][64];

    int tid = threadIdx.x;
    int tx = tid % 16;          // output cols tx*4 .. tx*4+3
    int ty = tid / 16;          // output rows ty*8 .. ty*8+7

    float acc[8][4];
#pragma unroll
    for (int i = 0; i < 8; i++)
#pragma unroll
        for (int j = 0; j < 4; j++) acc[i][j] = 0.f;

    for (int k0 = 0; k0 < NEMB; k0 += 16) {
        // A tile: 128x16
#pragma unroll
        for (int i = 0; i < 2; i++) {
            int lin = tid + i * 256;          // 0..511 float4s
            int row = lin >> 2;
            int c4  = lin & 3;
            float4 v = *(const float4*)(A + (size_t)row * NEMB + k0 + c4 * 4);
            As[c4 * 4 + 0][row] = v.x;
            As[c4 * 4 + 1][row] = v.y;
            As[c4 * 4 + 2][row] = v.z;
            As[c4 * 4 + 3][row] = v.w;
        }
        // B tile: 16x64
        {
            int row = tid >> 4;
            int c4  = tid & 15;
            *(float4*)&Bs[row][c4 * 4] = *(const float4*)(W + (size_t)(k0 + row) * HS + c4 * 4);
        }
        __syncthreads();
#pragma unroll
        for (int kk = 0; kk < 16; kk++) {
            float a[8], bb[4];
#pragma unroll
            for (int i = 0; i < 8; i++) a[i] = As[kk][ty * 8 + i];
#pragma unroll
            for (int j = 0; j < 4; j++) bb[j] = Bs[kk][tx * 4 + j];
#pragma unroll
            for (int i = 0; i < 8; i++)
#pragma unroll
                for (int j = 0; j < 4; j++) acc[i][j] += a[i] * bb[j];
        }
        __syncthreads();
    }
#pragma unroll
    for (int i = 0; i < 8; i++) {
        float4 v = make_float4(acc[i][0], acc[i][1], acc[i][2], acc[i][3]);
        *(float4*)(out + (size_t)(ty * 8 + i) * HS + tx * 4) = v;
    }
}

// ---------------- kernel 2: causal flash attention ----------------
// grid: (CTX/128, NH, BATCH), 128 threads, dynamic smem
// each thread owns one query row; K/V tiles of 64 keys in smem.
#define QPAD 17   // float4 row stride for q tile (conflict-free)
#define ATTN_SMEM (128*QPAD*16 + 2*64*64*4)

__global__ __launch_bounds__(128)
void attn_kernel()
{
    extern __shared__ float smem[];
    float* q_s = smem;                          // 128 rows x QPAD float4
    float* k_s = smem + 128 * QPAD * 4;         // 64 x 64 floats
    float* v_s = k_s + 64 * 64;                 // 64 x 64 floats

    int tid = threadIdx.x;
    int qt = blockIdx.x, h = blockIdx.y, b = blockIdx.z;
    int q0 = qt * 128;

    const float* qg = g_q + ((size_t)(b * NH + h) * CTX + q0) * HS;
    const float* kg = g_k + (size_t)(b * NH + h) * CTX * HS;
    const float* vg = g_v + (size_t)(b * NH + h) * CTX * HS;

    // load q tile (128x64) with padded rows
#pragma unroll
    for (int i = 0; i < 16; i++) {
        int lin = tid + i * 128;                // 0..2047 float4s
        int row = lin >> 4;
        int c4  = lin & 15;
        *(float4*)&q_s[(row * QPAD + c4) * 4] = *(const float4*)(qg + (size_t)row * HS + c4 * 4);
    }

    int row = q0 + tid;                         // global query index
    float m = -1e30f, l = 0.f;
    float4 acc[16];
#pragma unroll
    for (int i = 0; i < 16; i++) acc[i] = make_float4(0.f, 0.f, 0.f, 0.f);

    int nkt = (q0 + 127) / 64 + 1;
    for (int kt = 0; kt < nkt; kt++) {
        int kb = kt * 64;
        __syncthreads();
#pragma unroll
        for (int i = 0; i < 8; i++) {
            int lin = tid + i * 128;
            int r = lin >> 4, c4 = lin & 15;
            *(float4*)&k_s[r * 64 + c4 * 4] = *(const float4*)(kg + (size_t)(kb + r) * HS + c4 * 4);
            *(float4*)&v_s[r * 64 + c4 * 4] = *(const float4*)(vg + (size_t)(kb + r) * HS + c4 * 4);
        }
        __syncthreads();

        const float4* q4 = (const float4*)&q_s[tid * QPAD * 4];

        for (int jc = 0; jc < 4; jc++) {
            int kb2 = kb + jc * 16;
            if (kb2 > row) break;               // per-thread early out (no syncs inside)

            float s[16];
#pragma unroll
            for (int j = 0; j < 16; j++) s[j] = 0.f;

#pragma unroll
            for (int kk = 0; kk < 16; kk++) {
                float4 qv = q4[kk];
#pragma unroll
                for (int j = 0; j < 16; j++) {
                    float4 kv = *(const float4*)&k_s[(jc * 16 + j) * 64 + kk * 4];
                    s[j] += qv.x * kv.x + qv.y * kv.y + qv.z * kv.z + qv.w * kv.w;
                }
            }

            float mx = m;
#pragma unroll
            for (int j = 0; j < 16; j++) {
                float sv = s[j] * 0.125f;       // 1/sqrt(64)
                if (kb2 + j > row) sv = -1e30f;
                s[j] = sv;
                mx = fmaxf(mx, sv);
            }
            float corr = __expf(m - mx);
            m = mx;
            l *= corr;
#pragma unroll
            for (int i = 0; i < 16; i++) {
                acc[i].x *= corr; acc[i].y *= corr; acc[i].z *= corr; acc[i].w *= corr;
            }
#pragma unroll
            for (int j = 0; j < 16; j++) {
                float p = __expf(s[j] - m);
                l += p;
                const float4* v4 = (const float4*)&v_s[(jc * 16 + j) * 64];
#pragma unroll
                for (int i = 0; i < 16; i++) {
                    float4 vv = v4[i];
                    acc[i].x += p * vv.x; acc[i].y += p * vv.y;
                    acc[i].z += p * vv.z; acc[i].w += p * vv.w;
                }
            }
        }
    }

    float inv = 1.f / l;
    float* og = g_att + ((size_t)b * CTX + row) * DM + h * HS;
#pragma unroll
    for (int i = 0; i < 16; i++) {
        float4 o = make_float4(acc[i].x * inv, acc[i].y * inv, acc[i].z * inv, acc[i].w * inv);
        *(float4*)(og + i * 4) = o;
    }
}

// ---------------- kernel 3/4: FFN SGEMM 128x128x16, 8x8 per thread ----------------
template <bool RELU>
__global__ __launch_bounds__(256)
void sgemm_kernel(const float* __restrict__ A, const float* __restrict__ B,
                  const float* __restrict__ bias, float* __restrict__ Cm,
                  int M, int N, int K)
{
    __shared__ float As[16][128];
    __shared__ float Bs[16][128];

    int tid = threadIdx.x;
    int bx = blockIdx.x;    // N tile
    int by = blockIdx.y;    // M tile
    const float* Ab = A + (size_t)by * 128 * K;
    const float* Bb = B + (size_t)bx * 128;

    int tx = tid % 16, ty = tid / 16;
    float acc[8][8];
#pragma unroll
    for (int i = 0; i < 8; i++)
#pragma unroll
        for (int j = 0; j < 8; j++) acc[i][j] = 0.f;

    for (int k0 = 0; k0 < K; k0 += 16) {
#pragma unroll
        for (int i = 0; i < 2; i++) {
            int lin = tid + i * 256;           // 512 float4s = 128x16
            int r = lin >> 2, c4 = lin & 3;
            float4 v = *(const float4*)(Ab + (size_t)r * K + k0 + c4 * 4);
            As[c4 * 4 + 0][r] = v.x;
            As[c4 * 4 + 1][r] = v.y;
            As[c4 * 4 + 2][r] = v.z;
            As[c4 * 4 + 3][r] = v.w;
        }
#pragma unroll
        for (int i = 0; i < 2; i++) {
            int lin = tid + i * 256;           // 512 float4s = 16x128
            int r = lin >> 5, c4 = lin & 31;
            *(float4*)&Bs[r][c4 * 4] = *(const float4*)(Bb + (size_t)(k0 + r) * N + c4 * 4);
        }
        __syncthreads();
#pragma unroll
        for (int kk = 0; kk < 16; kk++) {
            float a[8], bb[8];
#pragma unroll
            for (int i = 0; i < 8; i++) a[i] = As[kk][ty * 8 + i];
#pragma unroll
            for (int j = 0; j < 8; j++) bb[j] = Bs[kk][tx * 8 + j];
#pragma unroll
            for (int i = 0; i < 8; i++)
#pragma unroll
                for (int j = 0; j < 8; j++) acc[i][j] += a[i] * bb[j];
        }
        __syncthreads();
    }

#pragma unroll
    for (int i = 0; i < 8; i++) {
        size_t r = (size_t)by * 128 + ty * 8 + i;
#pragma unroll
        for (int j4 = 0; j4 < 2; j4++) {
            int cc = bx * 128 + tx * 8 + j4 * 4;
            float4 o;
            o.x = acc[i][j4 * 4 + 0] + bias[cc + 0];
            o.y = acc[i][j4 * 4 + 1] + bias[cc + 1];
            o.z = acc[i][j4 * 4 + 2] + bias[cc + 2];
            o.w = acc[i][j4 * 4 + 3] + bias[cc + 3];
            if (RELU) {
                o.x = fmaxf(o.x, 0.f); o.y = fmaxf(o.y, 0.f);
                o.z = fmaxf(o.z, 0.f); o.w = fmaxf(o.w, 0.f);
            }
            *(float4*)(Cm + r * N + cc) = o;
        }
    }
}

// ---------------- launch ----------------
extern "C" void kernel_launch(void* const* d_in, const int* in_sizes, int n_in,
                              void* d_out, int out_size)
{
    const float* x  = (const float*)d_in[0];
    const float* Wq = (const float*)d_in[1];
    const float* Wk = (const float*)d_in[2];
    const float* Wv = (const float*)d_in[3];
    const float* W1 = (const float*)d_in[4];
    const float* b1 = (const float*)d_in[5];
    const float* W2 = (const float*)d_in[6];
    const float* b2 = (const float*)d_in[7];
    float* out = (float*)d_out;

    float* att = nullptr;
    float* hbuf = nullptr;
    cudaGetSymbolAddress((void**)&att, g_att);
    cudaGetSymbolAddress((void**)&hbuf, g_h);

    // 1) QKV projections
    qkv_kernel<<<dim3(CTX / 128, NH * 3, BATCH), 256>>>(x, Wq, Wk, Wv);

    // 2) causal attention -> g_att [B,T,H*D]
    cudaFuncSetAttribute(attn_kernel, cudaFuncAttributeMaxDynamicSharedMemorySize, ATTN_SMEM);
    attn_kernel<<<dim3(CTX / 128, NH, BATCH), 128, ATTN_SMEM>>>();

    // 3) FFN1: [8192,1024] @ [1024,4096] + b1
    sgemm_kernel<false><<<dim3(FF / 128, (BATCH * CTX) / 128), 256>>>(att, W1, b1, hbuf,
                                                                      BATCH * CTX, FF, DM);
    // 4) FFN2: [8192,4096] @ [4096,1024] + b2, then ReLU
    sgemm_kernel<true><<<dim3(DM / 128, (BATCH * CTX) / 128), 256>>>(hbuf, W2, b2, out,
                                                                     BATCH * CTX, DM, FF);
}

// round 3
// speedup vs baseline: 1.6991x; 1.6991x over previous
#include <cuda_runtime.h>
#include <cuda_bf16.h>
#include <cstdint>

#define BATCH 4
#define CTX   2048
#define NEMB  1024
#define NH    16
#define HS    64
#define DM    1024
#define FF    4096
#define MTOT  (BATCH*CTX)   // 8192

typedef __nv_bfloat16 bf16;

// ================= scratch =================
__device__ float g_q[(size_t)BATCH*NH*CTX*HS];
__device__ float g_k[(size_t)BATCH*NH*CTX*HS];
__device__ float g_v[(size_t)BATCH*NH*CTX*HS];
__device__ bf16 g_xhi[(size_t)MTOT*NEMB],  g_xlo[(size_t)MTOT*NEMB];
__device__ bf16 g_bqhi[(size_t)3*DM*NEMB], g_bqlo[(size_t)3*DM*NEMB];
__device__ bf16 g_ahi[(size_t)MTOT*DM],    g_alo[(size_t)MTOT*DM];
__device__ bf16 g_w1hi[(size_t)FF*DM],     g_w1lo[(size_t)FF*DM];
__device__ bf16 g_hhi[(size_t)MTOT*FF],    g_hlo[(size_t)MTOT*FF];
__device__ bf16 g_w2hi[(size_t)DM*FF],     g_w2lo[(size_t)DM*FF];

__device__ __forceinline__ uint32_t pack2bf(float a, float b) {
    __nv_bfloat162 p(__float2bfloat16(a), __float2bfloat16(b));
    return *reinterpret_cast<uint32_t*>(&p);
}
__device__ __forceinline__ uint32_t smem_u32(const void* p) {
    uint32_t a;
    asm("{ .reg .u64 t; cvta.to.shared.u64 t, %1; cvt.u32.u64 %0, t; }" : "=r"(a) : "l"(p));
    return a;
}
__device__ __forceinline__ void cp16(uint32_t dst, const void* src) {
    asm volatile("cp.async.cg.shared.global [%0], [%1], 16;" :: "r"(dst), "l"(src));
}
#define CP_COMMIT() asm volatile("cp.async.commit_group;" ::: "memory")
#define CP_WAIT(n)  asm volatile("cp.async.wait_group %0;" :: "n"(n) : "memory")

__device__ __forceinline__ void ldm4(uint32_t* r, uint32_t addr) {
    asm volatile("ldmatrix.sync.aligned.m8n8.x4.shared.b16 {%0,%1,%2,%3}, [%4];"
        : "=r"(r[0]), "=r"(r[1]), "=r"(r[2]), "=r"(r[3]) : "r"(addr));
}
__device__ __forceinline__ void mma_bf16(float* d, const uint32_t* a, const uint32_t* b) {
    asm volatile("mma.sync.aligned.m16n8k16.row.col.f32.bf16.bf16.f32 "
        "{%0,%1,%2,%3}, {%4,%5,%6,%7}, {%8,%9}, {%0,%1,%2,%3};"
        : "+f"(d[0]), "+f"(d[1]), "+f"(d[2]), "+f"(d[3])
        : "r"(a[0]), "r"(a[1]), "r"(a[2]), "r"(a[3]), "r"(b[0]), "r"(b[1]));
}

// ================= split / transpose kernels =================
__global__ __launch_bounds__(256) void split_x_kernel(const float* __restrict__ x,
                                                      bf16* __restrict__ hi, bf16* __restrict__ lo)
{
    size_t i = (size_t)blockIdx.x * 256 + threadIdx.x;   // float4 index
    float4 v = ((const float4*)x)[i];
    float h0 = __bfloat162float(__float2bfloat16(v.x));
    float h1 = __bfloat162float(__float2bfloat16(v.y));
    float h2 = __bfloat162float(__float2bfloat16(v.z));
    float h3 = __bfloat162float(__float2bfloat16(v.w));
    ((uint2*)hi)[i] = make_uint2(pack2bf(v.x, v.y), pack2bf(v.z, v.w));
    ((uint2*)lo)[i] = make_uint2(pack2bf(v.x - h0, v.y - h1), pack2bf(v.z - h2, v.w - h3));
}

// W [K,N] row-major -> out [N,K] bf16 hi/lo
__global__ __launch_bounds__(256) void transpose_split(const float* __restrict__ W,
                                                       bf16* __restrict__ hi, bf16* __restrict__ lo,
                                                       int K, int N)
{
    __shared__ float t[32][33];
    int n0 = blockIdx.x * 32, k0 = blockIdx.y * 32;
    int tx = threadIdx.x, ty = threadIdx.y;
#pragma unroll
    for (int i = ty; i < 32; i += 8)
        t[i][tx] = W[(size_t)(k0 + i) * N + n0 + tx];
    __syncthreads();
#pragma unroll
    for (int i = ty; i < 32; i += 8) {
        float v = t[tx][i];
        bf16 h = __float2bfloat16(v);
        size_t o = (size_t)(n0 + i) * K + k0 + tx;
        hi[o] = h;
        lo[o] = __float2bfloat16(v - __bfloat162float(h));
    }
}

// Wq/Wk/Wv [H,C,D] -> bqkv[n = sel*1024 + h*64 + d][k = c]
__global__ __launch_bounds__(256) void qkv_transpose_split(const float* __restrict__ Wq,
                                                           const float* __restrict__ Wk,
                                                           const float* __restrict__ Wv,
                                                           bf16* __restrict__ hi, bf16* __restrict__ lo)
{
    __shared__ float t[32][33];
    int sel = blockIdx.z >> 4, h = blockIdx.z & 15;
    const float* W = (sel == 0 ? Wq : sel == 1 ? Wk : Wv) + (size_t)h * NEMB * HS;
    int c0 = blockIdx.x * 32, d0 = blockIdx.y * 32;
    int tx = threadIdx.x, ty = threadIdx.y;
#pragma unroll
    for (int i = ty; i < 32; i += 8)
        t[i][tx] = W[(size_t)(c0 + i) * HS + d0 + tx];
    __syncthreads();
    int nbase = sel * DM + h * HS + d0;
#pragma unroll
    for (int i = ty; i < 32; i += 8) {
        float v = t[tx][i];
        bf16 hh = __float2bfloat16(v);
        size_t o = (size_t)(nbase + i) * NEMB + c0 + tx;
        hi[o] = hh;
        lo[o] = __float2bfloat16(v - __bfloat162float(hh));
    }
}

// ================= mma.sync split-bf16 GEMM =================
// D[m,n] = sum_k A[m,k]*B[n,k]  (B stored n-major [N][K])
// hi/lo split: AhiBhi + AhiBlo + AloBhi (lo*lo dropped, ~4e-6 rel)
// MODE 0: scatter fp32 -> g_q/g_k/g_v
// MODE 1: +bias, write split bf16 (FFN1 -> h)
// MODE 2: +bias, relu, write fp32 (FFN2 -> out)
#define ROWB    80          // padded row: 40 bf16 = 80 bytes (conflict-free ldmatrix)
#define TILE_B  (128*ROWB)  // 10240 bytes per operand tile
#define OFF_AH  0
#define OFF_AL  (TILE_B)
#define OFF_BH  (2*TILE_B)
#define OFF_BL  (3*TILE_B)
#define STAGE_B (4*TILE_B)  // 40960
#define NSTAGE  3
#define GEMM_SMEM (NSTAGE*STAGE_B)   // 122880

template <int MODE>
__global__ __launch_bounds__(256, 1)
void gemm_split(const bf16* __restrict__ Ahi, const bf16* __restrict__ Alo,
                const bf16* __restrict__ Bhi, const bf16* __restrict__ Blo,
                const float* __restrict__ bias,
                float* __restrict__ out_f, bf16* __restrict__ out_hi, bf16* __restrict__ out_lo,
                float* __restrict__ oq, float* __restrict__ ok, float* __restrict__ ov,
                int N, int K)
{
    extern __shared__ char smem[];
    uint32_t sb = smem_u32(smem);

    int tid = threadIdx.x, wid = tid >> 5, lid = tid & 31;
    int wm = wid >> 2, wn = wid & 3;          // warp tile: 64(M) x 32(N)
    int bx = blockIdx.x, by = blockIdx.y;

    const bf16* aH = Ahi + (size_t)by * 128 * K;
    const bf16* aL = Alo + (size_t)by * 128 * K;
    const bf16* bH = Bhi + (size_t)bx * 128 * K;
    const bf16* bL = Blo + (size_t)bx * 128 * K;

    // per-thread global-load geometry (2 x 16B chunks per operand per stage)
    int r0 = tid >> 2, c0 = tid & 3;          // chunk 0: row r0, 16B-chunk c0
    int r1 = (tid + 256) >> 2, c1 = (tid + 256) & 3;
    uint32_t so0 = (uint32_t)(r0 * ROWB + c0 * 16);
    uint32_t so1 = (uint32_t)(r1 * ROWB + c1 * 16);

    float acc[4][4][4];
#pragma unroll
    for (int i = 0; i < 4; i++)
#pragma unroll
        for (int j = 0; j < 4; j++)
#pragma unroll
            for (int l = 0; l < 4; l++) acc[i][j][l] = 0.f;

    int ITERS = K >> 5;

#define ISSUE(st, k0) do {                                                     \
        uint32_t _b = sb + (st) * STAGE_B;                                     \
        size_t _g0 = (size_t)r0 * K + (k0) + c0 * 8;                           \
        size_t _g1 = (size_t)r1 * K + (k0) + c1 * 8;                           \
        cp16(_b + OFF_AH + so0, aH + _g0); cp16(_b + OFF_AH + so1, aH + _g1);  \
        cp16(_b + OFF_AL + so0, aL + _g0); cp16(_b + OFF_AL + so1, aL + _g1);  \
        cp16(_b + OFF_BH + so0, bH + _g0); cp16(_b + OFF_BH + so1, bH + _g1);  \
        cp16(_b + OFF_BL + so0, bL + _g0); cp16(_b + OFF_BL + so1, bL + _g1);  \
    } while (0)

    ISSUE(0, 0);  CP_COMMIT();
    ISSUE(1, 32); CP_COMMIT();

    int g = lid >> 3, rr = lid & 7;
    // ldmatrix lane geometry
    uint32_t a_row_off = (uint32_t)(((g & 1) * 8 + rr) * ROWB + (g >> 1) * 16);
    uint32_t b_row_off = (uint32_t)(((g >> 1) * 8 + rr) * ROWB + (g & 1) * 16);

    for (int it = 0; it < ITERS; it++) {
        int pre = it + NSTAGE - 1;
        if (pre < ITERS) { ISSUE(pre % NSTAGE, pre * 32); }
        CP_COMMIT();
        CP_WAIT(NSTAGE - 2);
        __syncthreads();

        uint32_t base = sb + (it % NSTAGE) * STAGE_B;
#pragma unroll
        for (int ks = 0; ks < 2; ks++) {
            uint32_t ah[4][4], al[4][4], bh[2][4], bl[2][4];
#pragma unroll
            for (int mi = 0; mi < 4; mi++) {
                uint32_t off = (uint32_t)((wm * 64 + mi * 16) * ROWB + ks * 32) + a_row_off;
                ldm4(ah[mi], base + OFF_AH + off);
                ldm4(al[mi], base + OFF_AL + off);
            }
#pragma unroll
            for (int p = 0; p < 2; p++) {
                uint32_t off = (uint32_t)((wn * 32 + p * 16) * ROWB + ks * 32) + b_row_off;
                ldm4(bh[p], base + OFF_BH + off);
                ldm4(bl[p], base + OFF_BL + off);
            }
#pragma unroll
            for (int mi = 0; mi < 4; mi++)
#pragma unroll
                for (int ni = 0; ni < 4; ni++) {
                    int p = ni >> 1, o = (ni & 1) * 2;
                    mma_bf16(acc[mi][ni], ah[mi], &bh[p][o]);
                    mma_bf16(acc[mi][ni], ah[mi], &bl[p][o]);
                    mma_bf16(acc[mi][ni], al[mi], &bh[p][o]);
                }
        }
        __syncthreads();
    }
#undef ISSUE

    // ---------------- epilogue ----------------
    int t4 = lid >> 2, t2 = (lid & 3) * 2;
#pragma unroll
    for (int mi = 0; mi < 4; mi++) {
#pragma unroll
        for (int ni = 0; ni < 4; ni++) {
            int n = bx * 128 + wn * 32 + ni * 8 + t2;
            int m0 = by * 128 + wm * 64 + mi * 16 + t4;
            float bn0 = 0.f, bn1 = 0.f;
            if (MODE != 0) { bn0 = bias[n]; bn1 = bias[n + 1]; }
#pragma unroll
            for (int half = 0; half < 2; half++) {
                int m = m0 + half * 8;
                float v0 = acc[mi][ni][half * 2];
                float v1 = acc[mi][ni][half * 2 + 1];
                if (MODE == 0) {
                    int b = m >> 11, t = m & (CTX - 1);
                    int sel = n >> 10, hh = (n & 1023) >> 6, d0 = n & 63;
                    float* op = (sel == 0 ? oq : sel == 1 ? ok : ov)
                                + ((size_t)(b * NH + hh) * CTX + t) * HS + d0;
                    *(float2*)op = make_float2(v0, v1);
                } else if (MODE == 1) {
                    v0 += bn0; v1 += bn1;
                    float h0 = __bfloat162float(__float2bfloat16(v0));
                    float h1 = __bfloat162float(__float2bfloat16(v1));
                    size_t o = (size_t)m * N + n;
                    *(uint32_t*)(out_hi + o) = pack2bf(v0, v1);
                    *(uint32_t*)(out_lo + o) = pack2bf(v0 - h0, v1 - h1);
                } else {
                    v0 = fmaxf(v0 + bn0, 0.f);
                    v1 = fmaxf(v1 + bn1, 0.f);
                    *(float2*)(out_f + (size_t)m * N + n) = make_float2(v0, v1);
                }
            }
        }
    }
}

// ================= causal flash attention (fp32, split-bf16 epilogue) =================
#define QPAD 17
#define ATTN_SMEM (128*QPAD*16 + 2*64*64*4)

__global__ __launch_bounds__(128)
void attn_kernel()
{
    extern __shared__ float fsm[];
    float* q_s = fsm;
    float* k_s = fsm + 128 * QPAD * 4;
    float* v_s = k_s + 64 * 64;

    int tid = threadIdx.x;
    int qt = blockIdx.x, h = blockIdx.y, b = blockIdx.z;
    int q0 = qt * 128;

    const float* qg = g_q + ((size_t)(b * NH + h) * CTX + q0) * HS;
    const float* kg = g_k + (size_t)(b * NH + h) * CTX * HS;
    const float* vg = g_v + (size_t)(b * NH + h) * CTX * HS;

#pragma unroll
    for (int i = 0; i < 16; i++) {
        int lin = tid + i * 128;
        int row = lin >> 4, c4 = lin & 15;
        *(float4*)&q_s[(row * QPAD + c4) * 4] = *(const float4*)(qg + (size_t)row * HS + c4 * 4);
    }

    int row = q0 + tid;
    float m = -1e30f, l = 0.f;
    float4 acc[16];
#pragma unroll
    for (int i = 0; i < 16; i++) acc[i] = make_float4(0.f, 0.f, 0.f, 0.f);

    int nkt = (q0 + 127) / 64 + 1;
    for (int kt = 0; kt < nkt; kt++) {
        int kb = kt * 64;
        __syncthreads();
#pragma unroll
        for (int i = 0; i < 8; i++) {
            int lin = tid + i * 128;
            int r = lin >> 4, c4 = lin & 15;
            *(float4*)&k_s[r * 64 + c4 * 4] = *(const float4*)(kg + (size_t)(kb + r) * HS + c4 * 4);
            *(float4*)&v_s[r * 64 + c4 * 4] = *(const float4*)(vg + (size_t)(kb + r) * HS + c4 * 4);
        }
        __syncthreads();

        const float4* q4 = (const float4*)&q_s[tid * QPAD * 4];

        for (int jc = 0; jc < 4; jc++) {
            int kb2 = kb + jc * 16;
            if (kb2 > row) break;

            float s[16];
#pragma unroll
            for (int j = 0; j < 16; j++) s[j] = 0.f;
#pragma unroll
            for (int kk = 0; kk < 16; kk++) {
                float4 qv = q4[kk];
#pragma unroll
                for (int j = 0; j < 16; j++) {
                    float4 kv = *(const float4*)&k_s[(jc * 16 + j) * 64 + kk * 4];
                    s[j] += qv.x * kv.x + qv.y * kv.y + qv.z * kv.z + qv.w * kv.w;
                }
            }
            float mx = m;
#pragma unroll
            for (int j = 0; j < 16; j++) {
                float sv = s[j] * 0.125f;
                if (kb2 + j > row) sv = -1e30f;
                s[j] = sv;
                mx = fmaxf(mx, sv);
            }
            float corr = __expf(m - mx);
            m = mx;
            l *= corr;
#pragma unroll
            for (int i = 0; i < 16; i++) {
                acc[i].x *= corr; acc[i].y *= corr; acc[i].z *= corr; acc[i].w *= corr;
            }
#pragma unroll
            for (int j = 0; j < 16; j++) {
                float p = __expf(s[j] - m);
                l += p;
                const float4* v4 = (const float4*)&v_s[(jc * 16 + j) * 64];
#pragma unroll
                for (int i = 0; i < 16; i++) {
                    float4 vv = v4[i];
                    acc[i].x += p * vv.x; acc[i].y += p * vv.y;
                    acc[i].z += p * vv.z; acc[i].w += p * vv.w;
                }
            }
        }
    }

    float inv = 1.f / l;
    size_t obase = ((size_t)b * CTX + row) * DM + h * HS;
#pragma unroll
    for (int i = 0; i < 16; i++) {
        float v0 = acc[i].x * inv, v1 = acc[i].y * inv, v2 = acc[i].z * inv, v3 = acc[i].w * inv;
        float h0 = __bfloat162float(__float2bfloat16(v0));
        float h1 = __bfloat162float(__float2bfloat16(v1));
        float h2 = __bfloat162float(__float2bfloat16(v2));
        float h3 = __bfloat162float(__float2bfloat16(v3));
        *(uint2*)(g_ahi + obase + i * 4) = make_uint2(pack2bf(v0, v1), pack2bf(v2, v3));
        *(uint2*)(g_alo + obase + i * 4) = make_uint2(pack2bf(v0 - h0, v1 - h1), pack2bf(v2 - h2, v3 - h3));
    }
}

// ================= launch =================
extern "C" void kernel_launch(void* const* d_in, const int* in_sizes, int n_in,
                              void* d_out, int out_size)
{
    const float* x  = (const float*)d_in[0];
    const float* Wq = (const float*)d_in[1];
    const float* Wk = (const float*)d_in[2];
    const float* Wv = (const float*)d_in[3];
    const float* W1 = (const float*)d_in[4];
    const float* b1 = (const float*)d_in[5];
    const float* W2 = (const float*)d_in[6];
    const float* b2 = (const float*)d_in[7];
    float* out = (float*)d_out;

    float *qp, *kp, *vp;
    bf16 *xhi, *xlo, *bqhi, *bqlo, *ahi, *alo, *w1hi, *w1lo, *hhi, *hlo, *w2hi, *w2lo;
    cudaGetSymbolAddress((void**)&qp, g_q);
    cudaGetSymbolAddress((void**)&kp, g_k);
    cudaGetSymbolAddress((void**)&vp, g_v);
    cudaGetSymbolAddress((void**)&xhi, g_xhi);
    cudaGetSymbolAddress((void**)&xlo, g_xlo);
    cudaGetSymbolAddress((void**)&bqhi, g_bqhi);
    cudaGetSymbolAddress((void**)&bqlo, g_bqlo);
    cudaGetSymbolAddress((void**)&ahi, g_ahi);
    cudaGetSymbolAddress((void**)&alo, g_alo);
    cudaGetSymbolAddress((void**)&w1hi, g_w1hi);
    cudaGetSymbolAddress((void**)&w1lo, g_w1lo);
    cudaGetSymbolAddress((void**)&hhi, g_hhi);
    cudaGetSymbolAddress((void**)&hlo, g_hlo);
    cudaGetSymbolAddress((void**)&w2hi, g_w2hi);
    cudaGetSymbolAddress((void**)&w2lo, g_w2lo);

    cudaFuncSetAttribute(gemm_split<0>, cudaFuncAttributeMaxDynamicSharedMemorySize, GEMM_SMEM);
    cudaFuncSetAttribute(gemm_split<1>, cudaFuncAttributeMaxDynamicSharedMemorySize, GEMM_SMEM);
    cudaFuncSetAttribute(gemm_split<2>, cudaFuncAttributeMaxDynamicSharedMemorySize, GEMM_SMEM);
    cudaFuncSetAttribute(attn_kernel, cudaFuncAttributeMaxDynamicSharedMemorySize, ATTN_SMEM);

    // input conversions
    split_x_kernel<<<(size_t)MTOT * NEMB / 1024, 256>>>(x, xhi, xlo);
    qkv_transpose_split<<<dim3(NEMB / 32, HS / 32, 48), dim3(32, 8)>>>(Wq, Wk, Wv, bqhi, bqlo);
    transpose_split<<<dim3(FF / 32, DM / 32), dim3(32, 8)>>>(W1, w1hi, w1lo, DM, FF);
    transpose_split<<<dim3(DM / 32, FF / 32), dim3(32, 8)>>>(W2, w2hi, w2lo, FF, DM);

    // QKV: [8192,1024] @ [1024,3072] -> scatter to g_q/g_k/g_v
    gemm_split<0><<<dim3(3 * DM / 128, MTOT / 128), 256, GEMM_SMEM>>>(
        xhi, xlo, bqhi, bqlo, nullptr, nullptr, nullptr, nullptr, qp, kp, vp, 3 * DM, NEMB);

    // attention -> att hi/lo
    attn_kernel<<<dim3(CTX / 128, NH, BATCH), 128, ATTN_SMEM>>>();

    // FFN1: [8192,1024] @ [1024,4096] + b1 -> h hi/lo
    gemm_split<1><<<dim3(FF / 128, MTOT / 128), 256, GEMM_SMEM>>>(
        ahi, alo, w1hi, w1lo, b1, nullptr, hhi, hlo, nullptr, nullptr, nullptr, FF, DM);

    // FFN2: [8192,4096] @ [4096,1024] + b2, relu -> out
    gemm_split<2><<<dim3(DM / 128, MTOT / 128), 256, GEMM_SMEM>>>(
        hhi, hlo, w2hi, w2lo, b2, out, nullptr, nullptr, nullptr, nullptr, nullptr, DM, FF);
}